// round 12
// baseline (speedup 1.0000x reference)
#include <cuda_runtime.h>
#include <cstdint>

// ============================================================
// Shaw relative positional embedding:
//   out[b,h,n,r] = (1/8) * sum_d q[b,h,n,d] * E[n-r+2048, d]
// (clip is a no-op: |n-r| <= 2047)
//
// Per 128x128 output tile, banded GEMM with mma.sync m16n8k8 tf32.
// R12 changes vs R11 (attack issue-bound alu=41%):
//   * tf32 conversion hoisted out of the MMA loop: one vectorized
//     in-place pass per tile (Q warp-local after Q-bar; E cooperative
//     after E-bar). cvts/thread 320 -> 96; MMA loop is pure LDS+MMA.
//   * split mbarriers: Q convert + A-frag loads overlap E fill.
//   * per-warp epilogue: scatter -> fence -> own bulk stores; no
//     final block barrier.
// ============================================================

#define SEQ      2048
#define DHEAD    64
#define BH       32
#define TN       128
#define TR       128
#define BAND     256          // band rows staged
#define BROW     68           // band SMEM row stride (floats): 272B, conflict-free
#define QROW     68           // Q SMEM row stride (floats)
#define OROW     132          // staging row stride (floats): 528B = 33*16
#define THREADS  256
#define NI_PER_W 18           // n8 blocks per warp (band coverage)

// SMEM: [0,16) Q mbarrier; [16,32) E mbarrier; [32,+Bs) band; then Qs.
// Epilogue staging aliases Bs.
#define SMEM_QBAR   0
#define SMEM_EBAR   16
#define SMEM_OFF    32
#define BS_BYTES    (BAND * BROW * 4)              // 69632
#define QS_BYTES    (TN * QROW * 4)                // 34816
#define SMEM_BYTES  (SMEM_OFF + BS_BYTES + QS_BYTES)   // 104480
#define Q_FILL_BYTES (TN * DHEAD * 4)              // 32768
#define E_FILL_BYTES (BAND * DHEAD * 4)            // 65536

__device__ __forceinline__ uint32_t smem_u32addr(const void* p) {
    uint32_t a;
    asm("{ .reg .u64 t; cvta.to.shared.u64 t, %1; cvt.u32.u64 %0, t; }" : "=r"(a) : "l"(p));
    return a;
}

__device__ __forceinline__ uint32_t f2tf32(float f) {
    uint32_t r;
    asm("cvt.rna.tf32.f32 %0, %1;" : "=r"(r) : "f"(f));
    return r;
}

__device__ __forceinline__ void mma_16x8x8_tf32(float c[4],
                                                const uint32_t a[4],
                                                uint32_t b0, uint32_t b1) {
    asm volatile(
        "mma.sync.aligned.m16n8k8.row.col.f32.tf32.tf32.f32 "
        "{%0,%1,%2,%3}, {%4,%5,%6,%7}, {%8,%9}, {%0,%1,%2,%3};"
        : "+f"(c[0]), "+f"(c[1]), "+f"(c[2]), "+f"(c[3])
        : "r"(a[0]), "r"(a[1]), "r"(a[2]), "r"(a[3]), "r"(b0), "r"(b1));
}

__device__ __forceinline__ void bulk_g2s(uint32_t smem_dst, const void* gmem_src,
                                         uint32_t bytes, uint32_t mbar) {
    uint64_t g;
    asm("cvta.to.global.u64 %0, %1;" : "=l"(g) : "l"(gmem_src));
    asm volatile(
        "cp.async.bulk.shared::cta.global.mbarrier::complete_tx::bytes "
        "[%0], [%1], %2, [%3];"
        :: "r"(smem_dst), "l"(g), "r"(bytes), "r"(mbar) : "memory");
}

__device__ __forceinline__ void bulk_s2g(void* gmem_dst, uint32_t smem_src,
                                         uint32_t bytes) {
    uint64_t g;
    asm("cvta.to.global.u64 %0, %1;" : "=l"(g) : "l"(gmem_dst));
    asm volatile(
        "cp.async.bulk.global.shared::cta.bulk_group [%0], [%1], %2;"
        :: "l"(g), "r"(smem_src), "r"(bytes) : "memory");
}

__device__ __forceinline__ void mbar_wait(uint32_t mbar) {
    uint32_t done;
    asm volatile(
        "{\n\t.reg .pred p;\n\t"
        "mbarrier.try_wait.parity.acquire.cta.shared::cta.b64 p, [%1], 0;\n\t"
        "selp.b32 %0, 1, 0, p;\n\t}"
        : "=r"(done) : "r"(mbar) : "memory");
    if (!done) {
        asm volatile(
            "{\n\t.reg .pred P1;\n\t"
            "WAIT_LOOP_%=:\n\t"
            "mbarrier.try_wait.parity.acquire.cta.shared::cta.b64 P1, [%0], 0, 0x989680;\n\t"
            "@P1 bra.uni WAIT_DONE_%=;\n\t"
            "bra.uni WAIT_LOOP_%=;\n\t"
            "WAIT_DONE_%=:\n\t}"
            :: "r"(mbar) : "memory");
    }
}

__global__ void __launch_bounds__(THREADS, 2)
shaw_relpos_kernel(const float* __restrict__ q,
                   const float* __restrict__ emb,
                   float* __restrict__ out)
{
    extern __shared__ char smem_raw[];
    const uint32_t sb = smem_u32addr(smem_raw);

    uint32_t* Bs = (uint32_t*)(smem_raw + SMEM_OFF);            // [BAND][BROW]
    uint32_t* Qs = (uint32_t*)(smem_raw + SMEM_OFF + BS_BYTES); // [TN][QROW]
    float* outs  = (float*)(smem_raw + SMEM_OFF);               // staging (aliases Bs)

    const int tid  = threadIdx.x;
    const int w    = tid >> 5;                // warp id = 16-row block
    const int lane = tid & 31;
    const int gid  = lane >> 2;               // 0..7
    const int t    = lane & 3;                // 0..3

    const int n0 = blockIdx.y * TN;
    const int r0 = blockIdx.x * TR;
    const int bz = blockIdx.z;                       // b*16 + h
    const int j0 = n0 - r0 + 2048 - (TR - 1);        // band start row in E, [1, 3841]

    // ---- mbarrier init + async fills ----
    if (tid == 0) {
        asm volatile("mbarrier.init.shared.b64 [%0], %1;" :: "r"(sb + SMEM_QBAR), "r"(1) : "memory");
        asm volatile("mbarrier.init.shared.b64 [%0], %1;" :: "r"(sb + SMEM_EBAR), "r"(1) : "memory");
    }
    __syncthreads();
    if (tid == 0) {
        asm volatile("mbarrier.arrive.expect_tx.shared.b64 _, [%0], %1;"
                     :: "r"(sb + SMEM_QBAR), "r"((uint32_t)Q_FILL_BYTES) : "memory");
        asm volatile("mbarrier.arrive.expect_tx.shared.b64 _, [%0], %1;"
                     :: "r"(sb + SMEM_EBAR), "r"((uint32_t)E_FILL_BYTES) : "memory");
    }
    // Q tile: 128 rows x 256 B  (Q barrier)
    if (tid < TN) {
        const float* src = q + ((size_t)bz * SEQ + n0 + tid) * DHEAD;
        bulk_g2s(sb + SMEM_OFF + BS_BYTES + (uint32_t)tid * (QROW * 4), src,
                 DHEAD * 4, sb + SMEM_QBAR);
    }
    // E band: 256 rows x 256 B  (E barrier)
    {
        const float* src = emb + ((size_t)j0 + tid) * DHEAD;
        bulk_g2s(sb + SMEM_OFF + (uint32_t)tid * (BROW * 4), src,
                 DHEAD * 4, sb + SMEM_EBAR);
    }

    // ---- Q ready: warp-local tf32 conversion (rows 16w..16w+15), 1/8 folded ----
    mbar_wait(sb + SMEM_QBAR);
    {
        uint4* qv = (uint4*)Qs;                    // row stride 17 uint4
        #pragma unroll
        for (int i = 0; i < 8; i++) {              // 16 rows * 16 uint4 / 32 lanes
            const int idx = i * 32 + lane;
            const int row16 = idx >> 4, c = idx & 15;
            uint4* p = &qv[(w * 16 + row16) * 17 + c];
            float4 v = *(float4*)p;
            *p = make_uint4(f2tf32(0.125f * v.x), f2tf32(0.125f * v.y),
                            f2tf32(0.125f * v.z), f2tf32(0.125f * v.w));
        }
    }
    __syncwarp();

    // ---- A fragments (16 rows x K=64), pure LDS.32, conflict-free ----
    uint32_t a[8][4];
    {
        const uint32_t* q_lo = &Qs[(w * 16 + gid) * QROW];
        const uint32_t* q_hi = q_lo + 8 * QROW;
        #pragma unroll
        for (int k = 0; k < 8; k++) {
            const int c0 = k * 8 + t;
            a[k][0] = q_lo[c0];
            a[k][1] = q_hi[c0];
            a[k][2] = q_lo[c0 + 4];
            a[k][3] = q_hi[c0 + 4];
        }
    }

    // ---- E ready: cooperative tf32 conversion of the band ----
    mbar_wait(sb + SMEM_EBAR);
    {
        uint4* bv = (uint4*)Bs;                    // row stride 17 uint4
        #pragma unroll
        for (int i = 0; i < 16; i++) {             // 256 rows * 16 uint4 / 256 thr
            const int idx = i * THREADS + tid;
            const int row = idx >> 4, c = idx & 15;
            uint4* p = &bv[row * 17 + c];
            float4 v = *(float4*)p;
            *p = make_uint4(f2tf32(v.x), f2tf32(v.y), f2tf32(v.z), f2tf32(v.w));
        }
    }
    __syncthreads();

    // ---- Band-restricted MMA, pure LDS+MMA, accumulators in registers ----
    float acc[NI_PER_W][4];
    {
        const int ni_lo = 2 * w;
        #pragma unroll
        for (int nn = 0; nn < NI_PER_W; nn++) {
            acc[nn][0] = acc[nn][1] = acc[nn][2] = acc[nn][3] = 0.f;
            const uint32_t* brow = &Bs[((ni_lo + nn) * 8 + gid) * BROW];
            #pragma unroll
            for (int k = 0; k < 8; k++) {
                uint32_t b0 = brow[k * 8 + t];
                uint32_t b1 = brow[k * 8 + t + 4];
                mma_16x8x8_tf32(acc[nn], a[k], b0, b1);
            }
        }
    }
    __syncthreads();   // all warps done reading Bs before staging overwrite

    // ---- Per-warp epilogue: scatter -> fence -> own bulk stores ----
    // C frag: c0:(gid, cc) c1:(gid, cc+1) c2:(gid+8, cc) c3:(gid+8, cc+1), cc = ni*8+2t
    // rl = nl + 127 - col; bijective. Warp w owns staging rows [16w, 16w+16).
    {
        const int ni_lo = 2 * w;
        const int nlo = w * 16 + gid;
        float* s_lo = outs + (size_t)nlo * OROW;
        float* s_hi = s_lo + (size_t)8 * OROW;
        #pragma unroll
        for (int nn = 0; nn < NI_PER_W; nn++) {
            const int cc  = (ni_lo + nn) * 8 + t * 2;
            const int rl0 = nlo + 127 - cc;
            const int rl2 = rl0 + 8;
            if ((unsigned)rl0 < TR)       s_lo[rl0]     = acc[nn][0];
            if ((unsigned)(rl0 - 1) < TR) s_lo[rl0 - 1] = acc[nn][1];
            if ((unsigned)rl2 < TR)       s_hi[rl2]     = acc[nn][2];
            if ((unsigned)(rl2 - 1) < TR) s_hi[rl2 - 1] = acc[nn][3];
        }
    }
    asm volatile("fence.proxy.async.shared::cta;" ::: "memory");
    __syncwarp();

    if (lane < 16) {
        const int row = w * 16 + lane;
        float* dst = out + ((size_t)bz * SEQ + n0 + row) * SEQ + r0;
        bulk_s2g(dst, sb + SMEM_OFF + (uint32_t)row * (OROW * 4), TR * 4);
    }
    asm volatile("cp.async.bulk.commit_group;" ::: "memory");
    asm volatile("cp.async.bulk.wait_group 0;" ::: "memory");
}

// ---------------- launch ----------------

extern "C" void kernel_launch(void* const* d_in, const int* in_sizes, int n_in,
                              void* d_out, int out_size) {
    // metadata order: q [2,16,2048,64], k (unused), rel_pos_emb [4097,64]
    const float* q   = (const float*)d_in[0];
    const float* emb = (const float*)d_in[2];
    for (int i = 0; i < n_in; i++) {
        if (in_sizes[i] == 4097 * 64) emb = (const float*)d_in[i];
    }
    float* out = (float*)d_out;

    cudaFuncSetAttribute(shaw_relpos_kernel,
                         cudaFuncAttributeMaxDynamicSharedMemorySize, SMEM_BYTES);

    dim3 grid(SEQ / TR, SEQ / TN, BH);   // 16 x 16 x 32 = 8192 CTAs
    shaw_relpos_kernel<<<grid, THREADS, SMEM_BYTES>>>(q, emb, out);
}

// round 13
// speedup vs baseline: 1.6188x; 1.6188x over previous
#include <cuda_runtime.h>
#include <cstdint>

// ============================================================
// Shaw relative positional embedding:
//   out[b,h,n,r] = (1/8) * sum_d q[b,h,n,d] * E[n-r+2048, d]
// (clip is a no-op: |n-r| <= 2047)
//
// Per 128x128 output tile, banded GEMM with mma.sync m16n8k8 tf32.
// Base = R11 (217.5us). R13 single change: B band is permuted
// in-place after the TMA fill so each k-step's (b0,b1) fragment
// pair is adjacent -> MMA loop uses conflict-free LDS.64 and zero
// in-loop cvts. Per 8-word k-group: dst[2t+u] = tf32(src[t+4u]).
// MMA-phase issue slots/thread: ~720 -> ~384.
// ============================================================

#define SEQ      2048
#define DHEAD    64
#define BH       32
#define TN       128
#define TR       128
#define BAND     256          // band rows staged
#define BROW     72           // band SMEM row stride (floats): 288B, LDS.64 conflict-free
#define QROW     68           // Q SMEM row stride (floats)
#define OROW     132          // staging row stride (floats): 528B = 33*16
#define THREADS  256
#define NI_PER_W 18           // n8 blocks per warp (band coverage)

// SMEM: [0,16) mbarrier; [32,+Bs) band; then Qs. Staging aliases Bs.
#define SMEM_MBAR   0
#define SMEM_OFF    32
#define BS_BYTES    (BAND * BROW * 4)              // 73728
#define QS_BYTES    (TN * QROW * 4)                // 34816
#define SMEM_BYTES  (SMEM_OFF + BS_BYTES + QS_BYTES)   // 108576 (occ 2)
#define FILL_BYTES  (BAND * DHEAD * 4 + TN * DHEAD * 4)   // 98304

__device__ __forceinline__ uint32_t smem_u32addr(const void* p) {
    uint32_t a;
    asm("{ .reg .u64 t; cvta.to.shared.u64 t, %1; cvt.u32.u64 %0, t; }" : "=r"(a) : "l"(p));
    return a;
}

__device__ __forceinline__ uint32_t f2tf32(float f) {
    uint32_t r;
    asm("cvt.rna.tf32.f32 %0, %1;" : "=r"(r) : "f"(f));
    return r;
}

__device__ __forceinline__ void mma_16x8x8_tf32(float c[4],
                                                const uint32_t a[4],
                                                uint32_t b0, uint32_t b1) {
    asm volatile(
        "mma.sync.aligned.m16n8k8.row.col.f32.tf32.tf32.f32 "
        "{%0,%1,%2,%3}, {%4,%5,%6,%7}, {%8,%9}, {%0,%1,%2,%3};"
        : "+f"(c[0]), "+f"(c[1]), "+f"(c[2]), "+f"(c[3])
        : "r"(a[0]), "r"(a[1]), "r"(a[2]), "r"(a[3]), "r"(b0), "r"(b1));
}

__device__ __forceinline__ void bulk_g2s(uint32_t smem_dst, const void* gmem_src,
                                         uint32_t bytes, uint32_t mbar) {
    uint64_t g;
    asm("cvta.to.global.u64 %0, %1;" : "=l"(g) : "l"(gmem_src));
    asm volatile(
        "cp.async.bulk.shared::cta.global.mbarrier::complete_tx::bytes "
        "[%0], [%1], %2, [%3];"
        :: "r"(smem_dst), "l"(g), "r"(bytes), "r"(mbar) : "memory");
}

__device__ __forceinline__ void bulk_s2g(void* gmem_dst, uint32_t smem_src,
                                         uint32_t bytes) {
    uint64_t g;
    asm("cvta.to.global.u64 %0, %1;" : "=l"(g) : "l"(gmem_dst));
    asm volatile(
        "cp.async.bulk.global.shared::cta.bulk_group [%0], [%1], %2;"
        :: "l"(g), "r"(smem_src), "r"(bytes) : "memory");
}

__global__ void __launch_bounds__(THREADS, 2)
shaw_relpos_kernel(const float* __restrict__ q,
                   const float* __restrict__ emb,
                   float* __restrict__ out)
{
    extern __shared__ char smem_raw[];
    const uint32_t sb = smem_u32addr(smem_raw);
    const uint32_t mbar = sb + SMEM_MBAR;

    uint32_t* Bs = (uint32_t*)(smem_raw + SMEM_OFF);          // [BAND][BROW]
    float* Qs    = (float*)(smem_raw + SMEM_OFF + BS_BYTES);  // [TN][QROW] raw f32
    float* outs  = (float*)(smem_raw + SMEM_OFF);             // staging (aliases Bs)

    const int tid  = threadIdx.x;
    const int w    = tid >> 5;                // warp id = 16-row block
    const int lane = tid & 31;
    const int gid  = lane >> 2;               // 0..7
    const int t    = lane & 3;                // 0..3

    const int n0 = blockIdx.y * TN;
    const int r0 = blockIdx.x * TR;
    const int bz = blockIdx.z;                       // b*16 + h
    const int j0 = n0 - r0 + 2048 - (TR - 1);        // band start row in E, [1, 3841]

    // ---- mbarrier init, then async fills ----
    if (tid == 0) {
        asm volatile("mbarrier.init.shared.b64 [%0], %1;" :: "r"(mbar), "r"(1) : "memory");
    }
    __syncthreads();
    if (tid == 0) {
        asm volatile("mbarrier.arrive.expect_tx.shared.b64 _, [%0], %1;"
                     :: "r"(mbar), "r"((uint32_t)FILL_BYTES) : "memory");
    }
    // E band: 256 rows x 256 B into padded rows (dst stride 288B = 18*16)
    {
        const float* src = emb + ((size_t)j0 + tid) * DHEAD;
        bulk_g2s(sb + SMEM_OFF + (uint32_t)tid * (BROW * 4), src, DHEAD * 4, mbar);
    }
    // Q tile: 128 rows x 256 B
    if (tid < TN) {
        const float* src = q + ((size_t)bz * SEQ + n0 + tid) * DHEAD;
        bulk_g2s(sb + SMEM_OFF + BS_BYTES + (uint32_t)tid * (QROW * 4), src, DHEAD * 4, mbar);
    }
    // wait (parity 0)
    {
        uint32_t done;
        asm volatile(
            "{\n\t.reg .pred p;\n\t"
            "mbarrier.try_wait.parity.acquire.cta.shared::cta.b64 p, [%1], 0;\n\t"
            "selp.b32 %0, 1, 0, p;\n\t}"
            : "=r"(done) : "r"(mbar) : "memory");
        if (!done) {
            asm volatile(
                "{\n\t.reg .pred P1;\n\t"
                "WAIT_LOOP_%=:\n\t"
                "mbarrier.try_wait.parity.acquire.cta.shared::cta.b64 P1, [%0], 0, 0x989680;\n\t"
                "@P1 bra.uni WAIT_DONE_%=;\n\t"
                "bra.uni WAIT_LOOP_%=;\n\t"
                "WAIT_DONE_%=:\n\t}"
                :: "r"(mbar) : "memory");
        }
    }

    // ---- A fragments (16 rows x K=64) from SMEM, cvt.rna with 1/8 fold ----
    // m16n8k8 tf32 A: a0:(gid, 8k+t) a1:(gid+8, 8k+t) a2:(gid, 8k+t+4) a3:(gid+8, 8k+t+4)
    uint32_t a[8][4];
    {
        const float* q_lo = &Qs[(w * 16 + gid) * QROW];
        const float* q_hi = q_lo + 8 * QROW;
        #pragma unroll
        for (int k = 0; k < 8; k++) {
            const int c0 = k * 8 + t;
            a[k][0] = f2tf32(0.125f * q_lo[c0]);
            a[k][1] = f2tf32(0.125f * q_hi[c0]);
            a[k][2] = f2tf32(0.125f * q_lo[c0 + 4]);
            a[k][3] = f2tf32(0.125f * q_hi[c0 + 4]);
        }
    }

    // ---- In-place permute + tf32-convert the band ----
    // Per 8-word k-group: dst[2t+u] = tf32(src[t+4u]); each thread owns
    // whole groups (no cross-thread hazard). 2048 groups / 256 threads.
    #pragma unroll
    for (int i = 0; i < 8; i++) {
        const int idx = i * THREADS + tid;
        const int row = idx >> 3, kg = idx & 7;
        uint32_t* g = &Bs[row * BROW + kg * 8];
        float4 s0 = *(float4*)g;          // src words 0..3  (t=0..3, u=0)
        float4 s1 = *(float4*)(g + 4);    // src words 4..7  (t=0..3, u=1)
        uint4 d0 = make_uint4(f2tf32(s0.x), f2tf32(s1.x), f2tf32(s0.y), f2tf32(s1.y));
        uint4 d1 = make_uint4(f2tf32(s0.z), f2tf32(s1.z), f2tf32(s0.w), f2tf32(s1.w));
        *(uint4*)g       = d0;
        *(uint4*)(g + 4) = d1;
    }
    __syncthreads();

    // ---- Band-restricted MMA: 8 LDS.64 + 8 MMA per nn block ----
    float acc[NI_PER_W][4];
    {
        const int ni_lo = 2 * w;
        #pragma unroll
        for (int nn = 0; nn < NI_PER_W; nn++) {
            acc[nn][0] = acc[nn][1] = acc[nn][2] = acc[nn][3] = 0.f;
            const uint32_t* brow = &Bs[((ni_lo + nn) * 8 + gid) * BROW + 2 * t];
            #pragma unroll
            for (int k = 0; k < 8; k++) {
                uint2 b = *(const uint2*)&brow[8 * k];   // (b0, b1) adjacent
                mma_16x8x8_tf32(acc[nn], a[k], b.x, b.y);
            }
        }
    }
    __syncthreads();   // all warps done reading Bs before staging overwrite

    // ---- Scatter accumulators into SMEM staging (diag extraction) ----
    // C frag: c0:(gid, cc) c1:(gid, cc+1) c2:(gid+8, cc) c3:(gid+8, cc+1), cc = ni*8+2t
    // rl = nl + 127 - col; bijective onto the 128x128 tile. Scale already in A.
    {
        const int ni_lo = 2 * w;
        const int nlo = w * 16 + gid;       // rows nlo and nlo+8
        float* s_lo = outs + (size_t)nlo * OROW;
        float* s_hi = s_lo + (size_t)8 * OROW;
        #pragma unroll
        for (int nn = 0; nn < NI_PER_W; nn++) {
            const int cc  = (ni_lo + nn) * 8 + t * 2;
            const int rl0 = nlo + 127 - cc;          // row nlo,   col cc
            const int rl2 = rl0 + 8;                 // row nlo+8, col cc
            if ((unsigned)rl0 < TR)       s_lo[rl0]     = acc[nn][0];
            if ((unsigned)(rl0 - 1) < TR) s_lo[rl0 - 1] = acc[nn][1];
            if ((unsigned)rl2 < TR)       s_hi[rl2]     = acc[nn][2];
            if ((unsigned)(rl2 - 1) < TR) s_hi[rl2 - 1] = acc[nn][3];
        }
    }
    __syncthreads();
    asm volatile("fence.proxy.async.shared::cta;" ::: "memory");

    // ---- Per-row TMA bulk store: staging -> gmem (512 B rows) ----
    if (tid < TN) {
        float* dst = out + ((size_t)bz * SEQ + n0 + tid) * SEQ + r0;
        bulk_s2g(dst, sb + SMEM_OFF + (uint32_t)tid * (OROW * 4), TR * 4);
    }
    asm volatile("cp.async.bulk.commit_group;" ::: "memory");
    asm volatile("cp.async.bulk.wait_group 0;" ::: "memory");
}

// ---------------- launch ----------------

extern "C" void kernel_launch(void* const* d_in, const int* in_sizes, int n_in,
                              void* d_out, int out_size) {
    // metadata order: q [2,16,2048,64], k (unused), rel_pos_emb [4097,64]
    const float* q   = (const float*)d_in[0];
    const float* emb = (const float*)d_in[2];
    for (int i = 0; i < n_in; i++) {
        if (in_sizes[i] == 4097 * 64) emb = (const float*)d_in[i];
    }
    float* out = (float*)d_out;

    cudaFuncSetAttribute(shaw_relpos_kernel,
                         cudaFuncAttributeMaxDynamicSharedMemorySize, SMEM_BYTES);

    dim3 grid(SEQ / TR, SEQ / TN, BH);   // 16 x 16 x 32 = 8192 CTAs
    shaw_relpos_kernel<<<grid, THREADS, SMEM_BYTES>>>(q, emb, out);
}